// round 1
// baseline (speedup 1.0000x reference)
#include <cuda_runtime.h>
#include <math.h>

// Problem constants
#define NT 4096   // tokens (2*2048)
#define DM 1024   // d_model
#define NE 8      // experts
#define NH 2048   // hidden
// TOP_K = 2 hardcoded throughout

// ---------------------------------------------------------------------------
// Scratch (static device globals — no runtime allocation)
// ---------------------------------------------------------------------------
__device__ int   g_cnt[NE];                       // tokens per expert
__device__ int   g_tok[NE * NT];                  // packed (t<<1)|kslot per expert row
__device__ float g_wt[NT * 2];                    // routing weight per (token, kslot)
__device__ float g_h[(size_t)NE * NT * NH];       // swiglu hidden, grouped rows (256MB)
__device__ float g_y[(size_t)NT * 2 * DM];        // per-slot expert outputs (32MB)

// ---------------------------------------------------------------------------
// Init: zero per-expert counters
// ---------------------------------------------------------------------------
__global__ void init_kernel() {
    if (threadIdx.x < NE) g_cnt[threadIdx.x] = 0;
}

// ---------------------------------------------------------------------------
// Router: one warp per token. logits = x[t]·Wr, softmax, top-2.
// Append (token, slot) to each chosen expert's list (order-independent later).
// ---------------------------------------------------------------------------
__global__ void router_kernel(const float* __restrict__ x,
                              const float* __restrict__ wr) {
    int warp = (blockIdx.x * blockDim.x + threadIdx.x) >> 5;
    int lane = threadIdx.x & 31;
    if (warp >= NT) return;
    const int t = warp;

    float acc[NE];
#pragma unroll
    for (int e = 0; e < NE; e++) acc[e] = 0.f;

    const float* xr = x + (size_t)t * DM;
    for (int d = lane; d < DM; d += 32) {
        float xv = xr[d];
        const float* w = wr + (size_t)d * NE;
#pragma unroll
        for (int e = 0; e < NE; e++) acc[e] = fmaf(xv, w[e], acc[e]);
    }
#pragma unroll
    for (int e = 0; e < NE; e++) {
#pragma unroll
        for (int o = 16; o > 0; o >>= 1)
            acc[e] += __shfl_xor_sync(0xffffffffu, acc[e], o);
    }

    if (lane == 0) {
        float mx = acc[0];
#pragma unroll
        for (int e = 1; e < NE; e++) mx = fmaxf(mx, acc[e]);
        float p[NE];
        float s = 0.f;
#pragma unroll
        for (int e = 0; e < NE; e++) { p[e] = expf(acc[e] - mx); s += p[e]; }
        float inv = 1.f / s;

        // top-1 (lowest index wins ties, matching jax top_k)
        int e0 = 0; float v0 = p[0];
#pragma unroll
        for (int e = 1; e < NE; e++) if (p[e] > v0) { v0 = p[e]; e0 = e; }
        // top-2
        int e1 = -1; float v1 = -1.f;
#pragma unroll
        for (int e = 0; e < NE; e++)
            if (e != e0 && p[e] > v1) { v1 = p[e]; e1 = e; }

        g_wt[t * 2 + 0] = v0 * inv;
        g_wt[t * 2 + 1] = v1 * inv;
        int p0 = atomicAdd(&g_cnt[e0], 1);
        g_tok[e0 * NT + p0] = (t << 1);
        int p1 = atomicAdd(&g_cnt[e1], 1);
        g_tok[e1 * NT + p1] = (t << 1) | 1;
    }
}

// ---------------------------------------------------------------------------
// GEMM1 (fused w1/w3 + SwiGLU): for expert e, gathered rows of x times
// w1[e], w3[e]. Block tile 128 rows x 64 cols (per matrix), BK=8.
// 256 threads, each computes 4 rows x 8 cols for BOTH outputs.
// ---------------------------------------------------------------------------
__global__ void __launch_bounds__(256, 2)
gemm1_kernel(const float* __restrict__ x,
             const float* __restrict__ w1,
             const float* __restrict__ w3) {
    const int e    = blockIdx.z;
    const int n    = g_cnt[e];
    const int row0 = blockIdx.y * 128;
    if (row0 >= n) return;
    const int col0 = blockIdx.x * 64;

    __shared__ __align__(16) float As[8][128];
    __shared__ __align__(16) float Bs1[8][64];
    __shared__ __align__(16) float Bs3[8][64];

    const int tid = threadIdx.x;
    // A loads: 2 threads per row, float4 each (8 floats/row per k-tile)
    const int ar = tid >> 1;
    const int ac = (tid & 1) * 4;
    const float* aptr = nullptr;
    {
        int r = row0 + ar;
        if (r < n) aptr = x + (size_t)(g_tok[e * NT + r] >> 1) * DM + ac;
    }
    // B loads: 32 threads per k-row, float2 each
    const int bk = tid >> 5;
    const int bn = (tid & 31) * 2;
    const float* b1p = w1 + (size_t)e * DM * NH + (size_t)bk * NH + col0 + bn;
    const float* b3p = w3 + (size_t)e * DM * NH + (size_t)bk * NH + col0 + bn;

    const int tx = tid & 7;    // 8 col groups * 8 cols = 64
    const int ty = tid >> 3;   // 32 row groups * 4 rows = 128

    float acc1[4][8], acc3[4][8];
#pragma unroll
    for (int i = 0; i < 4; i++)
#pragma unroll
        for (int j = 0; j < 8; j++) { acc1[i][j] = 0.f; acc3[i][j] = 0.f; }

    for (int k0 = 0; k0 < DM; k0 += 8) {
        float4 av = aptr ? *(const float4*)(aptr + k0)
                         : make_float4(0.f, 0.f, 0.f, 0.f);
        float2 b1v = *(const float2*)(b1p + (size_t)k0 * NH);
        float2 b3v = *(const float2*)(b3p + (size_t)k0 * NH);
        __syncthreads();
        As[ac + 0][ar] = av.x; As[ac + 1][ar] = av.y;
        As[ac + 2][ar] = av.z; As[ac + 3][ar] = av.w;
        Bs1[bk][bn] = b1v.x; Bs1[bk][bn + 1] = b1v.y;
        Bs3[bk][bn] = b3v.x; Bs3[bk][bn + 1] = b3v.y;
        __syncthreads();
#pragma unroll
        for (int k = 0; k < 8; k++) {
            float4 a  = *(const float4*)&As[k][ty * 4];
            float4 u0 = *(const float4*)&Bs1[k][tx * 8];
            float4 u1 = *(const float4*)&Bs1[k][tx * 8 + 4];
            float4 v0 = *(const float4*)&Bs3[k][tx * 8];
            float4 v1 = *(const float4*)&Bs3[k][tx * 8 + 4];
            float aa[4]  = {a.x, a.y, a.z, a.w};
            float bb1[8] = {u0.x, u0.y, u0.z, u0.w, u1.x, u1.y, u1.z, u1.w};
            float bb3[8] = {v0.x, v0.y, v0.z, v0.w, v1.x, v1.y, v1.z, v1.w};
#pragma unroll
            for (int i = 0; i < 4; i++)
#pragma unroll
                for (int j = 0; j < 8; j++) {
                    acc1[i][j] = fmaf(aa[i], bb1[j], acc1[i][j]);
                    acc3[i][j] = fmaf(aa[i], bb3[j], acc3[i][j]);
                }
        }
    }

    // Epilogue: h = silu(h1) * h3
#pragma unroll
    for (int i = 0; i < 4; i++) {
        int r = row0 + ty * 4 + i;
        if (r < n) {
            float* hp = g_h + ((size_t)e * NT + r) * NH + col0 + tx * 8;
            float tmp[8];
#pragma unroll
            for (int j = 0; j < 8; j++) {
                float a1 = acc1[i][j];
                float sg = 1.f / (1.f + expf(-a1));
                tmp[j] = a1 * sg * acc3[i][j];
            }
            *(float4*)hp       = make_float4(tmp[0], tmp[1], tmp[2], tmp[3]);
            *(float4*)(hp + 4) = make_float4(tmp[4], tmp[5], tmp[6], tmp[7]);
        }
    }
}

// ---------------------------------------------------------------------------
// GEMM2: y = h · w2[e], scaled by routing weight into per-(token,slot) buffer.
// Block tile 128x128, BK=8, 256 threads, 8x8 per thread.
// ---------------------------------------------------------------------------
__global__ void __launch_bounds__(256, 2)
gemm2_kernel(const float* __restrict__ w2) {
    const int e    = blockIdx.z;
    const int n    = g_cnt[e];
    const int row0 = blockIdx.y * 128;
    if (row0 >= n) return;
    const int col0 = blockIdx.x * 128;

    __shared__ __align__(16) float As[8][128];
    __shared__ __align__(16) float Bs[8][128];

    const int tid = threadIdx.x;
    const int ar = tid >> 1;
    const int ac = (tid & 1) * 4;
    const float* aptr = nullptr;
    if (row0 + ar < n)
        aptr = g_h + ((size_t)e * NT + row0 + ar) * NH + ac;
    const int bk = tid >> 5;
    const int bn = (tid & 31) * 4;
    const float* bp = w2 + (size_t)e * NH * DM + (size_t)bk * DM + col0 + bn;

    const int tx = tid & 15;   // 16 * 8 = 128 cols
    const int ty = tid >> 4;   // 16 * 8 = 128 rows

    float acc[8][8];
#pragma unroll
    for (int i = 0; i < 8; i++)
#pragma unroll
        for (int j = 0; j < 8; j++) acc[i][j] = 0.f;

    for (int k0 = 0; k0 < NH; k0 += 8) {
        float4 av = aptr ? *(const float4*)(aptr + k0)
                         : make_float4(0.f, 0.f, 0.f, 0.f);
        float4 bv = *(const float4*)(bp + (size_t)k0 * DM);
        __syncthreads();
        As[ac + 0][ar] = av.x; As[ac + 1][ar] = av.y;
        As[ac + 2][ar] = av.z; As[ac + 3][ar] = av.w;
        *(float4*)&Bs[bk][bn] = bv;
        __syncthreads();
#pragma unroll
        for (int k = 0; k < 8; k++) {
            float4 a0 = *(const float4*)&As[k][ty * 8];
            float4 a1 = *(const float4*)&As[k][ty * 8 + 4];
            float4 b0 = *(const float4*)&Bs[k][tx * 8];
            float4 b1 = *(const float4*)&Bs[k][tx * 8 + 4];
            float aa[8] = {a0.x, a0.y, a0.z, a0.w, a1.x, a1.y, a1.z, a1.w};
            float bb[8] = {b0.x, b0.y, b0.z, b0.w, b1.x, b1.y, b1.z, b1.w};
#pragma unroll
            for (int i = 0; i < 8; i++)
#pragma unroll
                for (int j = 0; j < 8; j++)
                    acc[i][j] = fmaf(aa[i], bb[j], acc[i][j]);
        }
    }

#pragma unroll
    for (int i = 0; i < 8; i++) {
        int r = row0 + ty * 8 + i;
        if (r < n) {
            int packed = g_tok[e * NT + r];
            float w = g_wt[packed];
            float* yp = g_y + (size_t)packed * DM + col0 + tx * 8;
            *(float4*)yp       = make_float4(w * acc[i][0], w * acc[i][1],
                                             w * acc[i][2], w * acc[i][3]);
            *(float4*)(yp + 4) = make_float4(w * acc[i][4], w * acc[i][5],
                                             w * acc[i][6], w * acc[i][7]);
        }
    }
}

// ---------------------------------------------------------------------------
// Combine: out[t] = y[t, slot0] + y[t, slot1]  (deterministic, no atomics)
// ---------------------------------------------------------------------------
__global__ void combine_kernel(float* __restrict__ out) {
    const int n4 = NT * DM / 4;
    int i = blockIdx.x * blockDim.x + threadIdx.x;
    if (i < n4) {
        int t  = i / (DM / 4);
        int d4 = i - t * (DM / 4);
        const float4* y = (const float4*)g_y;
        float4 a = y[(size_t)(t * 2) * (DM / 4) + d4];
        float4 b = y[(size_t)(t * 2 + 1) * (DM / 4) + d4];
        float4 o;
        o.x = a.x + b.x; o.y = a.y + b.y; o.z = a.z + b.z; o.w = a.w + b.w;
        ((float4*)out)[i] = o;
    }
}

// ---------------------------------------------------------------------------
// Launch: inputs in metadata order: x, w_router, w1, w3, w2
// ---------------------------------------------------------------------------
extern "C" void kernel_launch(void* const* d_in, const int* in_sizes, int n_in,
                              void* d_out, int out_size) {
    const float* x  = (const float*)d_in[0];
    const float* wr = (const float*)d_in[1];
    const float* w1 = (const float*)d_in[2];
    const float* w3 = (const float*)d_in[3];
    const float* w2 = (const float*)d_in[4];
    float* out = (float*)d_out;

    init_kernel<<<1, 32>>>();
    router_kernel<<<NT / 8, 256>>>(x, wr);

    dim3 g1(NH / 64, NT / 128, NE);
    gemm1_kernel<<<g1, 256>>>(x, w1, w3);

    dim3 g2(DM / 128, NT / 128, NE);
    gemm2_kernel<<<g2, 256>>>(w2);

    combine_kernel<<<(NT * DM / 4 + 255) / 256, 256>>>(out);
}

// round 3
// speedup vs baseline: 1.7934x; 1.7934x over previous
#include <cuda_runtime.h>
#include <math.h>
#include <stdint.h>

#define NT 4096   // tokens
#define DM 1024   // d_model
#define NE 8      // experts
#define NH 2048   // hidden

// ---------------------------------------------------------------------------
// Scratch (static device globals — no runtime allocation)
// ---------------------------------------------------------------------------
__device__ int   g_cnt[NE];
__device__ int   g_tok[NE * NT];                  // packed (t<<1)|slot
__device__ float g_wt[NT * 2];
__device__ float g_h[(size_t)NE * NT * NH];       // swiglu hidden (grouped rows)
__device__ float g_y[(size_t)NT * 2 * DM];        // per-slot outputs

// ---------------------------------------------------------------------------
// tf32 helpers
// ---------------------------------------------------------------------------
__device__ __forceinline__ uint32_t f2tf32(float v) {
    uint32_t r;
    asm("cvt.rna.tf32.f32 %0, %1;" : "=r"(r) : "f"(v));
    return r;
}

__device__ __forceinline__ void mma_tf32(float* c, const uint32_t* a,
                                         const uint32_t* b) {
    asm volatile(
        "mma.sync.aligned.m16n8k8.row.col.f32.tf32.tf32.f32 "
        "{%0,%1,%2,%3}, {%4,%5,%6,%7}, {%8,%9}, {%0,%1,%2,%3};"
        : "+f"(c[0]), "+f"(c[1]), "+f"(c[2]), "+f"(c[3])
        : "r"(a[0]), "r"(a[1]), "r"(a[2]), "r"(a[3]), "r"(b[0]), "r"(b[1]));
}

// ---------------------------------------------------------------------------
// Init / Router
// ---------------------------------------------------------------------------
__global__ void init_kernel() {
    if (threadIdx.x < NE) g_cnt[threadIdx.x] = 0;
}

__global__ void router_kernel(const float* __restrict__ x,
                              const float* __restrict__ wr) {
    int warp = (blockIdx.x * blockDim.x + threadIdx.x) >> 5;
    int lane = threadIdx.x & 31;
    if (warp >= NT) return;
    const int t = warp;

    float acc[NE];
#pragma unroll
    for (int e = 0; e < NE; e++) acc[e] = 0.f;

    const float* xr = x + (size_t)t * DM;
    for (int d = lane; d < DM; d += 32) {
        float xv = xr[d];
        const float* w = wr + (size_t)d * NE;
#pragma unroll
        for (int e = 0; e < NE; e++) acc[e] = fmaf(xv, w[e], acc[e]);
    }
#pragma unroll
    for (int e = 0; e < NE; e++) {
#pragma unroll
        for (int o = 16; o > 0; o >>= 1)
            acc[e] += __shfl_xor_sync(0xffffffffu, acc[e], o);
    }

    if (lane == 0) {
        float mx = acc[0];
#pragma unroll
        for (int e = 1; e < NE; e++) mx = fmaxf(mx, acc[e]);
        float p[NE];
        float s = 0.f;
#pragma unroll
        for (int e = 0; e < NE; e++) { p[e] = expf(acc[e] - mx); s += p[e]; }
        float inv = 1.f / s;

        int e0 = 0; float v0 = p[0];
#pragma unroll
        for (int e = 1; e < NE; e++) if (p[e] > v0) { v0 = p[e]; e0 = e; }
        int e1 = -1; float v1 = -1.f;
#pragma unroll
        for (int e = 0; e < NE; e++)
            if (e != e0 && p[e] > v1) { v1 = p[e]; e1 = e; }

        g_wt[t * 2 + 0] = v0 * inv;
        g_wt[t * 2 + 1] = v1 * inv;
        int p0 = atomicAdd(&g_cnt[e0], 1);
        g_tok[e0 * NT + p0] = (t << 1);
        int p1 = atomicAdd(&g_cnt[e1], 1);
        g_tok[e1 * NT + p1] = (t << 1) | 1;
    }
}

// ---------------------------------------------------------------------------
// GEMM1 (tf32 tensor cores): gathered x rows times w1[e],w3[e], SwiGLU fused.
// Tile: BM=128, BN=64 per matrix, BK=16. 8 warps; warp = 32m x 32n x 2 mats.
// SMEM is stored in mma-FRAGMENT-major order (scatter at fill time) so the
// mainloop reads are one LDS.128 (A) / LDS.64 (B) per thread, conflict-free.
// ---------------------------------------------------------------------------
__global__ void __launch_bounds__(256)
gemm1_kernel(const float* __restrict__ x,
             const float* __restrict__ w1,
             const float* __restrict__ w3) {
    const int e    = blockIdx.z;
    const int n    = g_cnt[e];
    const int row0 = blockIdx.y * 128;
    if (row0 >= n) return;
    const int col0 = blockIdx.x * 64;

    // [buf][kstep][frag][lane][reg]
    __shared__ uint32_t As[2][2][8][32][4];    // 16 KB
    __shared__ uint32_t B1s[2][2][8][32][2];   // 8 KB
    __shared__ uint32_t B3s[2][2][8][32][2];   // 8 KB

    const int tid  = threadIdx.x;
    const int lane = tid & 31;
    const int w    = tid >> 5;
    const int wm   = w & 3;   // m-warp: mfrags 2wm..2wm+1
    const int wn   = w >> 2;  // n-warp: nfrags 4wn..4wn+3

    // A loader: thread owns row ar, 8 consecutive k at aq*8
    const int ar = tid >> 1;
    const int aq = tid & 1;
    const float* aptr = nullptr;
    if (row0 + ar < n)
        aptr = x + (size_t)(g_tok[e * NT + row0 + ar] >> 1) * DM + aq * 8;

    // B loader: thread owns k-row bk, 4 cols at bn0
    const int bk  = tid >> 4;
    const int bn0 = (tid & 15) * 4;
    const float* b1p = w1 + (size_t)e * DM * NH + (size_t)bk * NH + col0 + bn0;
    const float* b3p = w3 + (size_t)e * DM * NH + (size_t)bk * NH + col0 + bn0;

    float acc1[2][4][4], acc3[2][4][4];
#pragma unroll
    for (int i = 0; i < 2; i++)
#pragma unroll
        for (int j = 0; j < 4; j++)
#pragma unroll
            for (int r = 0; r < 4; r++) { acc1[i][j][r] = 0.f; acc3[i][j][r] = 0.f; }

    float4 avr0, avr1, b1r, b3r;
    const float4 fz = make_float4(0.f, 0.f, 0.f, 0.f);

#define G1_LOAD(k0)                                                       \
    do {                                                                  \
        avr0 = aptr ? *(const float4*)(aptr + (k0))     : fz;             \
        avr1 = aptr ? *(const float4*)(aptr + (k0) + 4) : fz;             \
        b1r  = *(const float4*)(b1p + (size_t)(k0) * NH);                 \
        b3r  = *(const float4*)(b3p + (size_t)(k0) * NH);                 \
    } while (0)

#define G1_STORE(buf)                                                     \
    do {                                                                  \
        const int mf = ar >> 4;                                           \
        const int rb = (ar >> 3) & 1;                                     \
        const int lb = (ar & 7) << 2;                                     \
        const float* av0 = (const float*)&avr0;                           \
        const float* av1 = (const float*)&avr1;                           \
        _Pragma("unroll")                                                 \
        for (int cc = 0; cc < 4; cc++) {                                  \
            As[buf][aq][mf][lb + cc][rb]     = f2tf32(av0[cc]);           \
            As[buf][aq][mf][lb + cc][rb + 2] = f2tf32(av1[cc]);           \
        }                                                                 \
        const int ks = bk >> 3;                                           \
        const int cr = (bk & 7) >> 2;                                     \
        const int nf = bn0 >> 3;                                          \
        const int lbb = ((bn0 & 7) << 2) + (bk & 3);                      \
        const float* b1a = (const float*)&b1r;                            \
        const float* b3a = (const float*)&b3r;                            \
        _Pragma("unroll")                                                 \
        for (int j = 0; j < 4; j++) {                                     \
            B1s[buf][ks][nf][lbb + j * 4][cr] = f2tf32(b1a[j]);           \
            B3s[buf][ks][nf][lbb + j * 4][cr] = f2tf32(b3a[j]);           \
        }                                                                 \
    } while (0)

    G1_LOAD(0);
    G1_STORE(0);
    __syncthreads();

#pragma unroll 1
    for (int k0 = 0; k0 < DM; k0 += 16) {
        const int buf = (k0 >> 4) & 1;
        const bool more = (k0 + 16) < DM;
        if (more) G1_LOAD(k0 + 16);
#pragma unroll
        for (int s = 0; s < 2; s++) {
            uint32_t a[2][4];
#pragma unroll
            for (int i = 0; i < 2; i++) {
                uint4 t4 = *(const uint4*)&As[buf][s][wm * 2 + i][lane][0];
                a[i][0] = t4.x; a[i][1] = t4.y; a[i][2] = t4.z; a[i][3] = t4.w;
            }
            uint32_t b1[4][2], b3[4][2];
#pragma unroll
            for (int j = 0; j < 4; j++) {
                uint2 u = *(const uint2*)&B1s[buf][s][wn * 4 + j][lane][0];
                b1[j][0] = u.x; b1[j][1] = u.y;
                uint2 v = *(const uint2*)&B3s[buf][s][wn * 4 + j][lane][0];
                b3[j][0] = v.x; b3[j][1] = v.y;
            }
#pragma unroll
            for (int i = 0; i < 2; i++)
#pragma unroll
                for (int j = 0; j < 4; j++) {
                    mma_tf32(acc1[i][j], a[i], b1[j]);
                    mma_tf32(acc3[i][j], a[i], b3[j]);
                }
        }
        if (more) G1_STORE(buf ^ 1);
        __syncthreads();
    }

    // Epilogue: h = silu(h1) * h3
    const int gq = lane >> 2;
    const int tq = lane & 3;
#pragma unroll
    for (int i = 0; i < 2; i++)
#pragma unroll
        for (int rh = 0; rh < 2; rh++) {
            int r = row0 + wm * 32 + i * 16 + rh * 8 + gq;
            if (r < n) {
                float* hp = g_h + ((size_t)e * NT + r) * NH + col0 + wn * 32;
#pragma unroll
                for (int j = 0; j < 4; j++) {
                    float x0 = acc1[i][j][rh * 2];
                    float x1 = acc1[i][j][rh * 2 + 1];
                    float h0 = x0 / (1.f + expf(-x0)) * acc3[i][j][rh * 2];
                    float h1 = x1 / (1.f + expf(-x1)) * acc3[i][j][rh * 2 + 1];
                    *(float2*)(hp + j * 8 + tq * 2) = make_float2(h0, h1);
                }
            }
        }
#undef G1_LOAD
#undef G1_STORE
}

// ---------------------------------------------------------------------------
// GEMM2 (tf32): y = h · w2[e] scaled by routing weight.
// Tile BM=128, BN=128, BK=16. 8 warps; warp = 32m x 64n.
// ---------------------------------------------------------------------------
__global__ void __launch_bounds__(256)
gemm2_kernel(const float* __restrict__ w2) {
    const int e    = blockIdx.z;
    const int n    = g_cnt[e];
    const int row0 = blockIdx.y * 128;
    if (row0 >= n) return;
    const int col0 = blockIdx.x * 128;

    __shared__ uint32_t As[2][2][8][32][4];    // 16 KB
    __shared__ uint32_t Bs[2][2][16][32][2];   // 16 KB

    const int tid  = threadIdx.x;
    const int lane = tid & 31;
    const int w    = tid >> 5;
    const int wm   = w & 3;   // mfrags 2wm..
    const int wn   = w >> 2;  // nfrags 8wn..

    const int ar = tid >> 1;
    const int aq = tid & 1;
    const float* aptr = nullptr;
    if (row0 + ar < n)
        aptr = g_h + ((size_t)e * NT + row0 + ar) * NH + aq * 8;

    const int bk  = tid >> 4;           // 0..15
    const int bn8 = (tid & 15) * 8;     // 0..120
    const float* bp = w2 + (size_t)e * NH * DM + (size_t)bk * DM + col0 + bn8;

    float acc[2][8][4];
#pragma unroll
    for (int i = 0; i < 2; i++)
#pragma unroll
        for (int j = 0; j < 8; j++)
#pragma unroll
            for (int r = 0; r < 4; r++) acc[i][j][r] = 0.f;

    float4 avr0, avr1, bvr0, bvr1;
    const float4 fz = make_float4(0.f, 0.f, 0.f, 0.f);

#define G2_LOAD(k0)                                                       \
    do {                                                                  \
        avr0 = aptr ? *(const float4*)(aptr + (k0))     : fz;             \
        avr1 = aptr ? *(const float4*)(aptr + (k0) + 4) : fz;             \
        bvr0 = *(const float4*)(bp + (size_t)(k0) * DM);                  \
        bvr1 = *(const float4*)(bp + (size_t)(k0) * DM + 4);              \
    } while (0)

#define G2_STORE(buf)                                                     \
    do {                                                                  \
        const int mf = ar >> 4;                                           \
        const int rb = (ar >> 3) & 1;                                     \
        const int lb = (ar & 7) << 2;                                     \
        const float* av0 = (const float*)&avr0;                           \
        const float* av1 = (const float*)&avr1;                           \
        _Pragma("unroll")                                                 \
        for (int cc = 0; cc < 4; cc++) {                                  \
            As[buf][aq][mf][lb + cc][rb]     = f2tf32(av0[cc]);           \
            As[buf][aq][mf][lb + cc][rb + 2] = f2tf32(av1[cc]);           \
        }                                                                 \
        const int ks = bk >> 3;                                           \
        const int cr = (bk & 7) >> 2;                                     \
        const int nf = tid & 15;                                          \
        const float* bv0 = (const float*)&bvr0;                           \
        const float* bv1 = (const float*)&bvr1;                           \
        _Pragma("unroll")                                                 \
        for (int j = 0; j < 4; j++) {                                     \
            Bs[buf][ks][nf][(bk & 3) + j * 4][cr]      = f2tf32(bv0[j]);  \
            Bs[buf][ks][nf][16 + (bk & 3) + j * 4][cr] = f2tf32(bv1[j]);  \
        }                                                                 \
    } while (0)

    G2_LOAD(0);
    G2_STORE(0);
    __syncthreads();

#pragma unroll 1
    for (int k0 = 0; k0 < NH; k0 += 16) {
        const int buf = (k0 >> 4) & 1;
        const bool more = (k0 + 16) < NH;
        if (more) G2_LOAD(k0 + 16);
#pragma unroll
        for (int s = 0; s < 2; s++) {
            uint32_t a[2][4];
#pragma unroll
            for (int i = 0; i < 2; i++) {
                uint4 t4 = *(const uint4*)&As[buf][s][wm * 2 + i][lane][0];
                a[i][0] = t4.x; a[i][1] = t4.y; a[i][2] = t4.z; a[i][3] = t4.w;
            }
            uint32_t b[8][2];
#pragma unroll
            for (int j = 0; j < 8; j++) {
                uint2 u = *(const uint2*)&Bs[buf][s][wn * 8 + j][lane][0];
                b[j][0] = u.x; b[j][1] = u.y;
            }
#pragma unroll
            for (int i = 0; i < 2; i++)
#pragma unroll
                for (int j = 0; j < 8; j++)
                    mma_tf32(acc[i][j], a[i], b[j]);
        }
        if (more) G2_STORE(buf ^ 1);
        __syncthreads();
    }

    const int gq = lane >> 2;
    const int tq = lane & 3;
#pragma unroll
    for (int i = 0; i < 2; i++)
#pragma unroll
        for (int rh = 0; rh < 2; rh++) {
            int r = row0 + wm * 32 + i * 16 + rh * 8 + gq;
            if (r < n) {
                int packed = g_tok[e * NT + r];
                float wt = g_wt[packed];
                float* yp = g_y + (size_t)packed * DM + col0 + wn * 64;
#pragma unroll
                for (int j = 0; j < 8; j++)
                    *(float2*)(yp + j * 8 + tq * 2) =
                        make_float2(wt * acc[i][j][rh * 2],
                                    wt * acc[i][j][rh * 2 + 1]);
            }
        }
#undef G2_LOAD
#undef G2_STORE
}

// ---------------------------------------------------------------------------
// Combine: out[t] = y[t,0] + y[t,1]
// ---------------------------------------------------------------------------
__global__ void combine_kernel(float* __restrict__ out) {
    const int n4 = NT * DM / 4;
    int i = blockIdx.x * blockDim.x + threadIdx.x;
    if (i < n4) {
        int t  = i / (DM / 4);
        int d4 = i - t * (DM / 4);
        const float4* y = (const float4*)g_y;
        float4 a = y[(size_t)(t * 2) * (DM / 4) + d4];
        float4 b = y[(size_t)(t * 2 + 1) * (DM / 4) + d4];
        float4 o;
        o.x = a.x + b.x; o.y = a.y + b.y; o.z = a.z + b.z; o.w = a.w + b.w;
        ((float4*)out)[i] = o;
    }
}

// ---------------------------------------------------------------------------
// Launch: inputs: x, w_router, w1, w3, w2
// ---------------------------------------------------------------------------
extern "C" void kernel_launch(void* const* d_in, const int* in_sizes, int n_in,
                              void* d_out, int out_size) {
    const float* x  = (const float*)d_in[0];
    const float* wr = (const float*)d_in[1];
    const float* w1 = (const float*)d_in[2];
    const float* w3 = (const float*)d_in[3];
    const float* w2 = (const float*)d_in[4];
    float* out = (float*)d_out;

    init_kernel<<<1, 32>>>();
    router_kernel<<<NT / 8, 256>>>(x, wr);

    dim3 g1(NH / 64, NT / 128, NE);
    gemm1_kernel<<<g1, 256>>>(x, w1, w3);

    dim3 g2(DM / 128, NT / 128, NE);
    gemm2_kernel<<<g2, 256>>>(w2);

    combine_kernel<<<(NT * DM / 4 + 255) / 256, 256>>>(out);
}

// round 4
// speedup vs baseline: 1.7953x; 1.0011x over previous
#include <cuda_runtime.h>
#include <math.h>
#include <stdint.h>

#define NT 4096   // tokens
#define DM 1024   // d_model
#define NE 8      // experts
#define NH 2048   // hidden

// ---------------------------------------------------------------------------
// Scratch (static device globals — no runtime allocation)
// ---------------------------------------------------------------------------
__device__ int   g_cnt[NE];
__device__ int   g_tok[NE * NT];                  // packed (t<<1)|slot
__device__ float g_wt[NT * 2];
__device__ float g_h[(size_t)NE * NT * NH];       // swiglu hidden (grouped rows)
__device__ float g_y[(size_t)NT * 2 * DM];        // per-slot outputs

// ---------------------------------------------------------------------------
// tf32 helpers
// ---------------------------------------------------------------------------
__device__ __forceinline__ uint32_t f2tf32(float v) {
    uint32_t r;
    asm("cvt.rna.tf32.f32 %0, %1;" : "=r"(r) : "f"(v));
    return r;
}

__device__ __forceinline__ void mma_tf32(float* c, const uint32_t* a,
                                         const uint32_t* b) {
    asm volatile(
        "mma.sync.aligned.m16n8k8.row.col.f32.tf32.tf32.f32 "
        "{%0,%1,%2,%3}, {%4,%5,%6,%7}, {%8,%9}, {%0,%1,%2,%3};"
        : "+f"(c[0]), "+f"(c[1]), "+f"(c[2]), "+f"(c[3])
        : "r"(a[0]), "r"(a[1]), "r"(a[2]), "r"(a[3]), "r"(b[0]), "r"(b[1]));
}

// ---------------------------------------------------------------------------
// Init / Router
// ---------------------------------------------------------------------------
__global__ void init_kernel() {
    if (threadIdx.x < NE) g_cnt[threadIdx.x] = 0;
}

__global__ void router_kernel(const float* __restrict__ x,
                              const float* __restrict__ wr) {
    int warp = (blockIdx.x * blockDim.x + threadIdx.x) >> 5;
    int lane = threadIdx.x & 31;
    if (warp >= NT) return;
    const int t = warp;

    float acc[NE];
#pragma unroll
    for (int e = 0; e < NE; e++) acc[e] = 0.f;

    const float* xr = x + (size_t)t * DM;
    for (int d = lane; d < DM; d += 32) {
        float xv = xr[d];
        const float* w = wr + (size_t)d * NE;
#pragma unroll
        for (int e = 0; e < NE; e++) acc[e] = fmaf(xv, w[e], acc[e]);
    }
#pragma unroll
    for (int e = 0; e < NE; e++) {
#pragma unroll
        for (int o = 16; o > 0; o >>= 1)
            acc[e] += __shfl_xor_sync(0xffffffffu, acc[e], o);
    }

    if (lane == 0) {
        float mx = acc[0];
#pragma unroll
        for (int e = 1; e < NE; e++) mx = fmaxf(mx, acc[e]);
        float p[NE];
        float s = 0.f;
#pragma unroll
        for (int e = 0; e < NE; e++) { p[e] = expf(acc[e] - mx); s += p[e]; }
        float inv = 1.f / s;

        int e0 = 0; float v0 = p[0];
#pragma unroll
        for (int e = 1; e < NE; e++) if (p[e] > v0) { v0 = p[e]; e0 = e; }
        int e1 = -1; float v1 = -1.f;
#pragma unroll
        for (int e = 0; e < NE; e++)
            if (e != e0 && p[e] > v1) { v1 = p[e]; e1 = e; }

        g_wt[t * 2 + 0] = v0 * inv;
        g_wt[t * 2 + 1] = v1 * inv;
        int p0 = atomicAdd(&g_cnt[e0], 1);
        g_tok[e0 * NT + p0] = (t << 1);
        int p1 = atomicAdd(&g_cnt[e1], 1);
        g_tok[e1 * NT + p1] = (t << 1) | 1;
    }
}

// ---------------------------------------------------------------------------
// GEMM1 (tf32 tensor cores): gathered x rows times w1[e],w3[e], SwiGLU fused.
// Tile: BM=128, BN=64 per matrix, BK=16. 8 warps; warp = 32m x 32n x 2 mats.
// SMEM is stored in mma-FRAGMENT-major order (scatter at fill time) so the
// mainloop reads are one LDS.128 (A) / LDS.64 (B) per thread, conflict-free.
// ---------------------------------------------------------------------------
__global__ void __launch_bounds__(256)
gemm1_kernel(const float* __restrict__ x,
             const float* __restrict__ w1,
             const float* __restrict__ w3) {
    const int e    = blockIdx.z;
    const int n    = g_cnt[e];
    const int row0 = blockIdx.y * 128;
    if (row0 >= n) return;
    const int col0 = blockIdx.x * 64;

    // [buf][kstep][frag][lane][reg]
    __shared__ uint32_t As[2][2][8][32][4];    // 16 KB
    __shared__ uint32_t B1s[2][2][8][32][2];   // 8 KB
    __shared__ uint32_t B3s[2][2][8][32][2];   // 8 KB

    const int tid  = threadIdx.x;
    const int lane = tid & 31;
    const int w    = tid >> 5;
    const int wm   = w & 3;   // m-warp: mfrags 2wm..2wm+1
    const int wn   = w >> 2;  // n-warp: nfrags 4wn..4wn+3

    // A loader: thread owns row ar, 8 consecutive k at aq*8
    const int ar = tid >> 1;
    const int aq = tid & 1;
    const float* aptr = nullptr;
    if (row0 + ar < n)
        aptr = x + (size_t)(g_tok[e * NT + row0 + ar] >> 1) * DM + aq * 8;

    // B loader: thread owns k-row bk, 4 cols at bn0
    const int bk  = tid >> 4;
    const int bn0 = (tid & 15) * 4;
    const float* b1p = w1 + (size_t)e * DM * NH + (size_t)bk * NH + col0 + bn0;
    const float* b3p = w3 + (size_t)e * DM * NH + (size_t)bk * NH + col0 + bn0;

    float acc1[2][4][4], acc3[2][4][4];
#pragma unroll
    for (int i = 0; i < 2; i++)
#pragma unroll
        for (int j = 0; j < 4; j++)
#pragma unroll
            for (int r = 0; r < 4; r++) { acc1[i][j][r] = 0.f; acc3[i][j][r] = 0.f; }

    float4 avr0, avr1, b1r, b3r;
    const float4 fz = make_float4(0.f, 0.f, 0.f, 0.f);

#define G1_LOAD(k0)                                                       \
    do {                                                                  \
        avr0 = aptr ? *(const float4*)(aptr + (k0))     : fz;             \
        avr1 = aptr ? *(const float4*)(aptr + (k0) + 4) : fz;             \
        b1r  = *(const float4*)(b1p + (size_t)(k0) * NH);                 \
        b3r  = *(const float4*)(b3p + (size_t)(k0) * NH);                 \
    } while (0)

#define G1_STORE(buf)                                                     \
    do {                                                                  \
        const int mf = ar >> 4;                                           \
        const int rb = (ar >> 3) & 1;                                     \
        const int lb = (ar & 7) << 2;                                     \
        const float* av0 = (const float*)&avr0;                           \
        const float* av1 = (const float*)&avr1;                           \
        _Pragma("unroll")                                                 \
        for (int cc = 0; cc < 4; cc++) {                                  \
            As[buf][aq][mf][lb + cc][rb]     = f2tf32(av0[cc]);           \
            As[buf][aq][mf][lb + cc][rb + 2] = f2tf32(av1[cc]);           \
        }                                                                 \
        const int ks = bk >> 3;                                           \
        const int cr = (bk & 7) >> 2;                                     \
        const int nf = bn0 >> 3;                                          \
        const int lbb = ((bn0 & 7) << 2) + (bk & 3);                      \
        const float* b1a = (const float*)&b1r;                            \
        const float* b3a = (const float*)&b3r;                            \
        _Pragma("unroll")                                                 \
        for (int j = 0; j < 4; j++) {                                     \
            B1s[buf][ks][nf][lbb + j * 4][cr] = f2tf32(b1a[j]);           \
            B3s[buf][ks][nf][lbb + j * 4][cr] = f2tf32(b3a[j]);           \
        }                                                                 \
    } while (0)

    G1_LOAD(0);
    G1_STORE(0);
    __syncthreads();

#pragma unroll 1
    for (int k0 = 0; k0 < DM; k0 += 16) {
        const int buf = (k0 >> 4) & 1;
        const bool more = (k0 + 16) < DM;
        if (more) G1_LOAD(k0 + 16);
#pragma unroll
        for (int s = 0; s < 2; s++) {
            uint32_t a[2][4];
#pragma unroll
            for (int i = 0; i < 2; i++) {
                uint4 t4 = *(const uint4*)&As[buf][s][wm * 2 + i][lane][0];
                a[i][0] = t4.x; a[i][1] = t4.y; a[i][2] = t4.z; a[i][3] = t4.w;
            }
            uint32_t b1[4][2], b3[4][2];
#pragma unroll
            for (int j = 0; j < 4; j++) {
                uint2 u = *(const uint2*)&B1s[buf][s][wn * 4 + j][lane][0];
                b1[j][0] = u.x; b1[j][1] = u.y;
                uint2 v = *(const uint2*)&B3s[buf][s][wn * 4 + j][lane][0];
                b3[j][0] = v.x; b3[j][1] = v.y;
            }
#pragma unroll
            for (int i = 0; i < 2; i++)
#pragma unroll
                for (int j = 0; j < 4; j++) {
                    mma_tf32(acc1[i][j], a[i], b1[j]);
                    mma_tf32(acc3[i][j], a[i], b3[j]);
                }
        }
        if (more) G1_STORE(buf ^ 1);
        __syncthreads();
    }

    // Epilogue: h = silu(h1) * h3
    const int gq = lane >> 2;
    const int tq = lane & 3;
#pragma unroll
    for (int i = 0; i < 2; i++)
#pragma unroll
        for (int rh = 0; rh < 2; rh++) {
            int r = row0 + wm * 32 + i * 16 + rh * 8 + gq;
            if (r < n) {
                float* hp = g_h + ((size_t)e * NT + r) * NH + col0 + wn * 32;
#pragma unroll
                for (int j = 0; j < 4; j++) {
                    float x0 = acc1[i][j][rh * 2];
                    float x1 = acc1[i][j][rh * 2 + 1];
                    float h0 = x0 / (1.f + expf(-x0)) * acc3[i][j][rh * 2];
                    float h1 = x1 / (1.f + expf(-x1)) * acc3[i][j][rh * 2 + 1];
                    *(float2*)(hp + j * 8 + tq * 2) = make_float2(h0, h1);
                }
            }
        }
#undef G1_LOAD
#undef G1_STORE
}

// ---------------------------------------------------------------------------
// GEMM2 (tf32): y = h · w2[e] scaled by routing weight.
// Tile BM=128, BN=128, BK=16. 8 warps; warp = 32m x 64n.
// ---------------------------------------------------------------------------
__global__ void __launch_bounds__(256)
gemm2_kernel(const float* __restrict__ w2) {
    const int e    = blockIdx.z;
    const int n    = g_cnt[e];
    const int row0 = blockIdx.y * 128;
    if (row0 >= n) return;
    const int col0 = blockIdx.x * 128;

    __shared__ uint32_t As[2][2][8][32][4];    // 16 KB
    __shared__ uint32_t Bs[2][2][16][32][2];   // 16 KB

    const int tid  = threadIdx.x;
    const int lane = tid & 31;
    const int w    = tid >> 5;
    const int wm   = w & 3;   // mfrags 2wm..
    const int wn   = w >> 2;  // nfrags 8wn..

    const int ar = tid >> 1;
    const int aq = tid & 1;
    const float* aptr = nullptr;
    if (row0 + ar < n)
        aptr = g_h + ((size_t)e * NT + row0 + ar) * NH + aq * 8;

    const int bk  = tid >> 4;           // 0..15
    const int bn8 = (tid & 15) * 8;     // 0..120
    const float* bp = w2 + (size_t)e * NH * DM + (size_t)bk * DM + col0 + bn8;

    float acc[2][8][4];
#pragma unroll
    for (int i = 0; i < 2; i++)
#pragma unroll
        for (int j = 0; j < 8; j++)
#pragma unroll
            for (int r = 0; r < 4; r++) acc[i][j][r] = 0.f;

    float4 avr0, avr1, bvr0, bvr1;
    const float4 fz = make_float4(0.f, 0.f, 0.f, 0.f);

#define G2_LOAD(k0)                                                       \
    do {                                                                  \
        avr0 = aptr ? *(const float4*)(aptr + (k0))     : fz;             \
        avr1 = aptr ? *(const float4*)(aptr + (k0) + 4) : fz;             \
        bvr0 = *(const float4*)(bp + (size_t)(k0) * DM);                  \
        bvr1 = *(const float4*)(bp + (size_t)(k0) * DM + 4);              \
    } while (0)

#define G2_STORE(buf)                                                     \
    do {                                                                  \
        const int mf = ar >> 4;                                           \
        const int rb = (ar >> 3) & 1;                                     \
        const int lb = (ar & 7) << 2;                                     \
        const float* av0 = (const float*)&avr0;                           \
        const float* av1 = (const float*)&avr1;                           \
        _Pragma("unroll")                                                 \
        for (int cc = 0; cc < 4; cc++) {                                  \
            As[buf][aq][mf][lb + cc][rb]     = f2tf32(av0[cc]);           \
            As[buf][aq][mf][lb + cc][rb + 2] = f2tf32(av1[cc]);           \
        }                                                                 \
        const int ks = bk >> 3;                                           \
        const int cr = (bk & 7) >> 2;                                     \
        const int nf = tid & 15;                                          \
        const float* bv0 = (const float*)&bvr0;                           \
        const float* bv1 = (const float*)&bvr1;                           \
        _Pragma("unroll")                                                 \
        for (int j = 0; j < 4; j++) {                                     \
            Bs[buf][ks][nf][(bk & 3) + j * 4][cr]      = f2tf32(bv0[j]);  \
            Bs[buf][ks][nf][16 + (bk & 3) + j * 4][cr] = f2tf32(bv1[j]);  \
        }                                                                 \
    } while (0)

    G2_LOAD(0);
    G2_STORE(0);
    __syncthreads();

#pragma unroll 1
    for (int k0 = 0; k0 < NH; k0 += 16) {
        const int buf = (k0 >> 4) & 1;
        const bool more = (k0 + 16) < NH;
        if (more) G2_LOAD(k0 + 16);
#pragma unroll
        for (int s = 0; s < 2; s++) {
            uint32_t a[2][4];
#pragma unroll
            for (int i = 0; i < 2; i++) {
                uint4 t4 = *(const uint4*)&As[buf][s][wm * 2 + i][lane][0];
                a[i][0] = t4.x; a[i][1] = t4.y; a[i][2] = t4.z; a[i][3] = t4.w;
            }
            uint32_t b[8][2];
#pragma unroll
            for (int j = 0; j < 8; j++) {
                uint2 u = *(const uint2*)&Bs[buf][s][wn * 8 + j][lane][0];
                b[j][0] = u.x; b[j][1] = u.y;
            }
#pragma unroll
            for (int i = 0; i < 2; i++)
#pragma unroll
                for (int j = 0; j < 8; j++)
                    mma_tf32(acc[i][j], a[i], b[j]);
        }
        if (more) G2_STORE(buf ^ 1);
        __syncthreads();
    }

    const int gq = lane >> 2;
    const int tq = lane & 3;
#pragma unroll
    for (int i = 0; i < 2; i++)
#pragma unroll
        for (int rh = 0; rh < 2; rh++) {
            int r = row0 + wm * 32 + i * 16 + rh * 8 + gq;
            if (r < n) {
                int packed = g_tok[e * NT + r];
                float wt = g_wt[packed];
                float* yp = g_y + (size_t)packed * DM + col0 + wn * 64;
#pragma unroll
                for (int j = 0; j < 8; j++)
                    *(float2*)(yp + j * 8 + tq * 2) =
                        make_float2(wt * acc[i][j][rh * 2],
                                    wt * acc[i][j][rh * 2 + 1]);
            }
        }
#undef G2_LOAD
#undef G2_STORE
}

// ---------------------------------------------------------------------------
// Combine: out[t] = y[t,0] + y[t,1]
// ---------------------------------------------------------------------------
__global__ void combine_kernel(float* __restrict__ out) {
    const int n4 = NT * DM / 4;
    int i = blockIdx.x * blockDim.x + threadIdx.x;
    if (i < n4) {
        int t  = i / (DM / 4);
        int d4 = i - t * (DM / 4);
        const float4* y = (const float4*)g_y;
        float4 a = y[(size_t)(t * 2) * (DM / 4) + d4];
        float4 b = y[(size_t)(t * 2 + 1) * (DM / 4) + d4];
        float4 o;
        o.x = a.x + b.x; o.y = a.y + b.y; o.z = a.z + b.z; o.w = a.w + b.w;
        ((float4*)out)[i] = o;
    }
}

// ---------------------------------------------------------------------------
// Launch: inputs: x, w_router, w1, w3, w2
// ---------------------------------------------------------------------------
extern "C" void kernel_launch(void* const* d_in, const int* in_sizes, int n_in,
                              void* d_out, int out_size) {
    const float* x  = (const float*)d_in[0];
    const float* wr = (const float*)d_in[1];
    const float* w1 = (const float*)d_in[2];
    const float* w3 = (const float*)d_in[3];
    const float* w2 = (const float*)d_in[4];
    float* out = (float*)d_out;

    init_kernel<<<1, 32>>>();
    router_kernel<<<NT / 8, 256>>>(x, wr);

    dim3 g1(NH / 64, NT / 128, NE);
    gemm1_kernel<<<g1, 256>>>(x, w1, w3);

    dim3 g2(DM / 128, NT / 128, NE);
    gemm2_kernel<<<g2, 256>>>(w2);

    combine_kernel<<<(NT * DM / 4 + 255) / 256, 256>>>(out);
}